// round 9
// baseline (speedup 1.0000x reference)
#include <cuda_runtime.h>
#include <cstdint>

#define N_NODES 40000
#define N_EDGES 640000
#define IN_CH   128
#define OUT_CH  128
#define NUM_RBF 64
#define TILE64  64
#define NT64    (N_EDGES / TILE64)     // 10000

// ---------------- device scratch (no allocs allowed) ----------------
__device__ float g_h[(size_t)N_NODES * OUT_CH];      // x @ Wl + bl

// ---------------- helpers ----------------
__device__ __forceinline__ float rnd_tf32(float x) {
    float r;
    asm("cvt.rna.tf32.f32 %0, %1;" : "=f"(r) : "f"(x));
    return r;
}
__device__ __forceinline__ uint32_t tf32_bits(float x) {
    return __float_as_uint(rnd_tf32(x));
}
__device__ __forceinline__ uint32_t smem_u32(const void* p) {
    uint32_t a;
    asm("{ .reg .u64 t; cvta.to.shared.u64 t, %1; cvt.u32.u64 %0, t; }"
        : "=r"(a) : "l"(p));
    return a;
}
__device__ __forceinline__ void red_add_v4(float* addr, float4 v) {
    asm volatile("red.global.add.v4.f32 [%0], {%1,%2,%3,%4};"
                 :: "l"(addr), "f"(v.x), "f"(v.y), "f"(v.z), "f"(v.w) : "memory");
}
__device__ __forceinline__ void cp16(uint32_t saddr, const void* g) {
    asm volatile("cp.async.cg.shared.global [%0], [%1], 16;"
                 :: "r"(saddr), "l"(g) : "memory");
}
__device__ __forceinline__ void cp_commit() {
    asm volatile("cp.async.commit_group;" ::: "memory");
}
__device__ __forceinline__ void cp_wait1() {
    asm volatile("cp.async.wait_group 1;" ::: "memory");
}
__device__ __forceinline__ void l2_prefetch(const float* p) {
    asm volatile("prefetch.global.L2 [%0];" :: "l"(p));
}
// mma.sync m16n8k8 tf32 (baseline PTX, sm_80+)
__device__ __forceinline__ void mma_tf32(float d[4], const uint32_t a[4],
                                         uint32_t b0, uint32_t b1) {
    asm volatile(
        "mma.sync.aligned.m16n8k8.row.col.f32.tf32.tf32.f32 "
        "{%0,%1,%2,%3}, {%4,%5,%6,%7}, {%8,%9}, {%0,%1,%2,%3};"
        : "+f"(d[0]), "+f"(d[1]), "+f"(d[2]), "+f"(d[3])
        : "r"(a[0]), "r"(a[1]), "r"(a[2]), "r"(a[3]), "r"(b0), "r"(b1));
}
__device__ __forceinline__ void ldsm_x4(uint32_t a[4], uint32_t saddr) {
    asm volatile("ldmatrix.sync.aligned.m8n8.x4.shared.b16 {%0,%1,%2,%3}, [%4];"
                 : "=r"(a[0]), "=r"(a[1]), "=r"(a[2]), "=r"(a[3]) : "r"(saddr));
}

// ---------------------------------------------------------------------------
// node linear: h = x @ Wl + bl via tf32 mma (unchanged, proven)
// ---------------------------------------------------------------------------
#define NL_LDX 132
#define NL_SMEM_BYTES (128 * NL_LDX * 4)

__global__ void __launch_bounds__(256)
node_linear_mma(const float* __restrict__ x, const float* __restrict__ Wl,
                const float* __restrict__ bl, float* __restrict__ h) {
    extern __shared__ float s_x[];
    const int tid = threadIdx.x;
    const int wid = tid >> 5, lane = tid & 31;
    const int qr = lane >> 2, tig = lane & 3;
    const int nb = wid * 16;
    const int m0 = blockIdx.x * 128;
    const uint32_t sx_u32 = smem_u32(s_x);
    const uint32_t a_off = ((lane & 15) * NL_LDX + ((lane >> 4) << 2)) * 4u;

    uint32_t wf[16][2][2];
#pragma unroll
    for (int ks = 0; ks < 16; ks++)
#pragma unroll
        for (int nt = 0; nt < 2; nt++) {
            int n = nb + nt * 8 + qr;
            wf[ks][nt][0] = tf32_bits(Wl[(size_t)(ks * 8 + tig) * OUT_CH + n]);
            wf[ks][nt][1] = tf32_bits(Wl[(size_t)(ks * 8 + tig + 4) * OUT_CH + n]);
        }
    float bias[4];
#pragma unroll
    for (int nt = 0; nt < 2; nt++)
#pragma unroll
        for (int p = 0; p < 2; p++)
            bias[nt * 2 + p] = bl[nb + nt * 8 + tig * 2 + p];

    for (int i = tid; i < 128 * 32; i += 256) {
        int r = i >> 5, q = i & 31;
        float4 v = make_float4(0.f, 0.f, 0.f, 0.f);
        if (m0 + r < N_NODES)
            v = *(const float4*)(x + (size_t)(m0 + r) * IN_CH + q * 4);
        v.x = rnd_tf32(v.x); v.y = rnd_tf32(v.y);
        v.z = rnd_tf32(v.z); v.w = rnd_tf32(v.w);
        *(float4*)(s_x + r * NL_LDX + q * 4) = v;
    }
    __syncthreads();

    float acc[16][4];
#pragma unroll
    for (int mt = 0; mt < 8; mt++)
#pragma unroll
        for (int nt = 0; nt < 2; nt++) {
            acc[mt * 2 + nt][0] = bias[nt * 2];
            acc[mt * 2 + nt][1] = bias[nt * 2 + 1];
            acc[mt * 2 + nt][2] = bias[nt * 2];
            acc[mt * 2 + nt][3] = bias[nt * 2 + 1];
        }
#pragma unroll
    for (int ks = 0; ks < 16; ks++) {
#pragma unroll
        for (int mt = 0; mt < 8; mt++) {
            uint32_t a[4];
            ldsm_x4(a, sx_u32 + (uint32_t)(mt * 16 * NL_LDX + ks * 8) * 4u + a_off);
            mma_tf32(acc[mt * 2 + 0], a, wf[ks][0][0], wf[ks][0][1]);
            mma_tf32(acc[mt * 2 + 1], a, wf[ks][1][0], wf[ks][1][1]);
        }
    }
#pragma unroll
    for (int mt = 0; mt < 8; mt++)
#pragma unroll
        for (int nt = 0; nt < 2; nt++) {
            int col = nb + nt * 8 + tig * 2;
            int r0 = m0 + mt * 16 + qr;
            float* a = acc[mt * 2 + nt];
            if (r0 < N_NODES)
                *(float2*)(h + (size_t)r0 * OUT_CH + col) = make_float2(a[0], a[1]);
            if (r0 + 8 < N_NODES)
                *(float2*)(h + (size_t)(r0 + 8) * OUT_CH + col) = make_float2(a[2], a[3]);
        }
}

// ---------------------------------------------------------------------------
// persistent edge kernel, LOW-REGISTER version:
//   W1/W2 live in smem as precomputed per-lane b-fragment images (uint2):
//     image[(ks*16 + n8)*32 + lane] = { W[ks*8+tig][n8*8+qr], W[ks*8+tig+4][...] }
//   (lane-consecutive uint2 -> conflict-free LDS.64)
//   Tile = 64 edges, 8 warps as 2M x 4N (warp: M=32, N=32), acc = 32 regs.
// smem floats:
//   rbf0 4352 | rbf1 4352 | H 8448 | OUT 8448 | W1 8192 | W2 16384 |
//   idx0 128 | idx1 128 | b1 128 | b2 128  == 50688 floats = 202.7 KB
// ---------------------------------------------------------------------------
#define LDR 68
#define LDH 132
#define S_RBF0 0
#define S_RBF1 4352
#define S_H    8704
#define S_OUT  17152
#define S_W1   25600
#define S_W2   33792
#define S_IDX0 50176
#define S_IDX1 50304
#define S_B1   50432
#define S_B2   50560
#define SM_FLOATS 50688
#define SM_BYTES (SM_FLOATS * 4)

__device__ __forceinline__ void prefetch64(uint32_t sb, int buf,
                                           const float* __restrict__ rbf,
                                           const int* __restrict__ eidx,
                                           int tile, int tid) {
    const size_t e0 = (size_t)tile * TILE64;
    const uint32_t rb = sb + (uint32_t)(S_RBF0 + buf * 4352) * 4u;
#pragma unroll
    for (int i = tid; i < 1024; i += 256) {
        int r = i >> 4, q = i & 15;
        cp16(rb + (uint32_t)(r * LDR + q * 4) * 4u,
             rbf + (e0 + r) * NUM_RBF + q * 4);
    }
    const uint32_t ib = sb + (uint32_t)(S_IDX0 + buf * 128) * 4u;
    if (tid < 16)
        cp16(ib + tid * 16u, eidx + e0 + tid * 4);
    else if (tid < 32)
        cp16(ib + 256u + (tid - 16) * 16u,
             eidx + (size_t)N_EDGES + e0 + (tid - 16) * 4);
}

__global__ void __launch_bounds__(256, 1)
edge_kernel_lr(const float* __restrict__ rbf, const int* __restrict__ eidx,
               const float* __restrict__ W1, const float* __restrict__ b1g,
               const float* __restrict__ W2, const float* __restrict__ b2g,
               const float* __restrict__ h, float* __restrict__ out,
               int n_ctas) {
    extern __shared__ float sm[];
    const uint32_t sbase = smem_u32(sm);
    float* s_H   = sm + S_H;
    float* s_out = sm + S_OUT;
    uint2* w1s   = (uint2*)(sm + S_W1);
    uint2* w2s   = (uint2*)(sm + S_W2);
    float* s_b1  = sm + S_B1;
    float* s_b2  = sm + S_B2;

    const int tid  = threadIdx.x;
    const int wid  = tid >> 5, lane = tid & 31;
    const int qr   = lane >> 2, tig = lane & 3;
    const int mg   = wid >> 2;          // M group: rows mg*32 .. mg*32+31
    const int ng   = wid & 3;           // N group: cols ng*32 .. ng*32+31

    const uint32_t aoff_r = ((lane & 15) * LDR + ((lane >> 4) << 2)) * 4u;
    const uint32_t aoff_h = ((lane & 15) * LDH + ((lane >> 4) << 2)) * 4u;
    const uint32_t sH_u32 = sbase + (uint32_t)S_H * 4u;

    // ---- one-time: build W fragment images + biases in smem ----
    for (int i = tid; i < 8 * 16 * 32; i += 256) {
        int ks = i >> 9, r = (i >> 5) & 15, ln = i & 31;
        int tg = ln & 3, q = ln >> 2;
        int k0 = ks * 8 + tg, n = r * 8 + q;
        w1s[i] = make_uint2(tf32_bits(W1[(size_t)k0 * OUT_CH + n]),
                            tf32_bits(W1[(size_t)(k0 + 4) * OUT_CH + n]));
    }
    for (int i = tid; i < 16 * 16 * 32; i += 256) {
        int ks = i >> 9, r = (i >> 5) & 15, ln = i & 31;
        int tg = ln & 3, q = ln >> 2;
        int k0 = ks * 8 + tg, n = r * 8 + q;
        w2s[i] = make_uint2(tf32_bits(W2[(size_t)k0 * OUT_CH + n]),
                            tf32_bits(W2[(size_t)(k0 + 4) * OUT_CH + n]));
    }
    if (tid < 128) { s_b1[tid] = b1g[tid]; s_b2[tid] = b2g[tid]; }

    int buf = 0;
    prefetch64(sbase, 0, rbf, eidx, blockIdx.x, tid);
    cp_commit();

    for (int tile = blockIdx.x; tile < NT64; tile += n_ctas) {
        int nx = tile + n_ctas;
        if (nx >= NT64) nx = tile;
        prefetch64(sbase, buf ^ 1, rbf, eidx, nx, tid);
        cp_commit();
        cp_wait1();
        __syncthreads();   // also orders one-time W-image build on iter 0

        int* s_dst = (int*)(sm + S_IDX0 + buf * 128);
        int* s_src = s_dst + 64;

        // L2-prefetch this tile's h rows (2 GEMMs of lead time)
        {
            int e = tid >> 2;
            l2_prefetch(h + (size_t)s_src[e] * OUT_CH + (tid & 3) * 32);
        }

        const uint32_t sR = sbase + (uint32_t)(S_RBF0 + buf * 4352) * 4u;

        // ---- GEMM1: H = relu(RBF @ W1 + b1); warp tile M=32 x N=32, K=64 ----
        {
            float acc[2][4][4];
#pragma unroll
            for (int mt = 0; mt < 2; mt++)
#pragma unroll
                for (int n8 = 0; n8 < 4; n8++)
#pragma unroll
                    for (int q = 0; q < 4; q++) acc[mt][n8][q] = 0.f;
#pragma unroll
            for (int ks = 0; ks < 8; ks++) {
                uint32_t a0[4], a1[4];
                ldsm_x4(a0, sR + (uint32_t)((mg * 32 + 0) * LDR + ks * 8) * 4u + aoff_r);
                ldsm_x4(a1, sR + (uint32_t)((mg * 32 + 16) * LDR + ks * 8) * 4u + aoff_r);
#pragma unroll
                for (int n8 = 0; n8 < 4; n8++) {
                    uint2 b = w1s[(ks * 16 + ng * 4 + n8) * 32 + lane];
                    mma_tf32(acc[0][n8], a0, b.x, b.y);
                    mma_tf32(acc[1][n8], a1, b.x, b.y);
                }
            }
#pragma unroll
            for (int n8 = 0; n8 < 4; n8++) {
                int col = ng * 32 + n8 * 8 + tig * 2;
                float2 bz = *(const float2*)(s_b1 + col);
#pragma unroll
                for (int mt = 0; mt < 2; mt++) {
                    int r0 = mg * 32 + mt * 16 + qr;
                    float* a = acc[mt][n8];
                    *(float2*)(s_H + r0 * LDH + col) =
                        make_float2(rnd_tf32(fmaxf(a[0] + bz.x, 0.f)),
                                    rnd_tf32(fmaxf(a[1] + bz.y, 0.f)));
                    *(float2*)(s_H + (r0 + 8) * LDH + col) =
                        make_float2(rnd_tf32(fmaxf(a[2] + bz.x, 0.f)),
                                    rnd_tf32(fmaxf(a[3] + bz.y, 0.f)));
                }
            }
        }
        __syncthreads();

        // ---- GEMM2: Wt = H @ W2 + b2; warp tile M=32 x N=32, K=128 ----
        {
            float acc[2][4][4];
#pragma unroll
            for (int mt = 0; mt < 2; mt++)
#pragma unroll
                for (int n8 = 0; n8 < 4; n8++)
#pragma unroll
                    for (int q = 0; q < 4; q++) acc[mt][n8][q] = 0.f;
#pragma unroll
            for (int ks = 0; ks < 16; ks++) {
                uint32_t a0[4], a1[4];
                ldsm_x4(a0, sH_u32 + (uint32_t)((mg * 32 + 0) * LDH + ks * 8) * 4u + aoff_h);
                ldsm_x4(a1, sH_u32 + (uint32_t)((mg * 32 + 16) * LDH + ks * 8) * 4u + aoff_h);
#pragma unroll
                for (int n8 = 0; n8 < 4; n8++) {
                    uint2 b = w2s[(ks * 16 + ng * 4 + n8) * 32 + lane];
                    mma_tf32(acc[0][n8], a0, b.x, b.y);
                    mma_tf32(acc[1][n8], a1, b.x, b.y);
                }
            }
#pragma unroll
            for (int n8 = 0; n8 < 4; n8++) {
                int col = ng * 32 + n8 * 8 + tig * 2;
                float2 bz = *(const float2*)(s_b2 + col);
#pragma unroll
                for (int mt = 0; mt < 2; mt++) {
                    int r0 = mg * 32 + mt * 16 + qr;
                    float* a = acc[mt][n8];
                    *(float2*)(s_out + r0 * LDH + col) =
                        make_float2(a[0] + bz.x, a[1] + bz.y);
                    *(float2*)(s_out + (r0 + 8) * LDH + col) =
                        make_float2(a[2] + bz.x, a[3] + bz.y);
                }
            }
        }
        __syncthreads();

        // ---- phase3: warp owns 8 edges; batched gather, red.v4 scatter ----
#pragma unroll
        for (int half = 0; half < 2; half++) {
            float4 hv[4];
            int dst4[4];
#pragma unroll
            for (int u = 0; u < 4; u++) {
                int e = wid * 8 + half * 4 + u;
                dst4[u] = s_dst[e];
                hv[u] = *(const float4*)(h + (size_t)s_src[e] * OUT_CH + lane * 4);
            }
#pragma unroll
            for (int u = 0; u < 4; u++) {
                int e = wid * 8 + half * 4 + u;
                float4 wv = *(const float4*)(s_out + e * LDH + lane * 4);
                red_add_v4(out + (size_t)dst4[u] * OUT_CH + lane * 4,
                           make_float4(hv[u].x * wv.x, hv[u].y * wv.y,
                                       hv[u].z * wv.z, hv[u].w * wv.w));
            }
        }
        // Race guard (R6 lesson): next prefetch overwrites this buffer.
        __syncthreads();
        buf ^= 1;
    }
}

// ---------------------------------------------------------------------------
extern "C" void kernel_launch(void* const* d_in, const int* in_sizes, int n_in,
                              void* d_out, int out_size) {
    const float* x    = (const float*)d_in[0];
    const int*   eidx = (const int*)d_in[1];
    const float* rbf  = (const float*)d_in[2];
    const float* W1   = (const float*)d_in[3];
    const float* b1   = (const float*)d_in[4];
    const float* W2   = (const float*)d_in[5];
    const float* b2   = (const float*)d_in[6];
    const float* Wl   = (const float*)d_in[7];
    const float* bl   = (const float*)d_in[8];
    float* out = (float*)d_out;

    static float* h_ptr = nullptr;
    static int n_sms = 0;
    if (!h_ptr) {
        cudaGetSymbolAddress((void**)&h_ptr, g_h);
        cudaDeviceGetAttribute(&n_sms, cudaDevAttrMultiProcessorCount, 0);
        cudaFuncSetAttribute(edge_kernel_lr,
                             cudaFuncAttributeMaxDynamicSharedMemorySize, SM_BYTES);
        cudaFuncSetAttribute(node_linear_mma,
                             cudaFuncAttributeMaxDynamicSharedMemorySize, NL_SMEM_BYTES);
    }

    cudaMemsetAsync(d_out, 0, (size_t)N_NODES * OUT_CH * sizeof(float), 0);
    node_linear_mma<<<(N_NODES + 127) / 128, 256, NL_SMEM_BYTES>>>(x, Wl, bl, h_ptr);
    edge_kernel_lr<<<n_sms, 256, SM_BYTES>>>(rbf, eidx, W1, b1, W2, b2,
                                             h_ptr, out, n_sms);
}